// round 1
// baseline (speedup 1.0000x reference)
#include <cuda_runtime.h>

#define SEQ   8192
#define HD    1024
#define G4    4096
#define NIN   64
#define NLAYER 5
#define NCTA  128

// ---------------- scratch (device globals; no allocation allowed) ------------
__device__ float    g_bufA[(size_t)SEQ * HD];   // 32 MB activation ping
__device__ float    g_bufB[(size_t)SEQ * HD];   // 32 MB activation pong
__device__ float    g_Z[(size_t)SEQ * G4];      // 128 MB input-projection buffer
__device__ float    g_h[2 * HD];                // double-buffered hidden state
__device__ unsigned g_counter;                  // monotonic step counter

// ---------------- math helpers ----------------------------------------------
__device__ __forceinline__ float sigmf(float x) { return 1.0f / (1.0f + __expf(-x)); }
__device__ __forceinline__ float tanh_fast(float x) { return 1.0f - 2.0f / (__expf(2.0f * x) + 1.0f); }

__device__ __forceinline__ unsigned ld_acq(const unsigned* p) {
    unsigned v;
    asm volatile("ld.acquire.gpu.global.b32 %0, [%1];" : "=r"(v) : "l"(p) : "memory");
    return v;
}

// ---------------- init: reset counter ----------------------------------------
__global__ void k_init() { g_counter = 0u; }

// ---------------- first layer: leaky_relu(x @ w1^T + b1) ---------------------
// block: 64 timesteps x 64 hidden. 256 threads: thread = (h in [0,64), tq in [0,4)) -> 16 t each.
__global__ __launch_bounds__(256) void k_first(const float* __restrict__ x,
                                               const float* __restrict__ w1,
                                               const float* __restrict__ b1,
                                               float* __restrict__ out) {
    __shared__ float xs[64][NIN];       // 16 KB
    __shared__ float ws[64][NIN + 1];   // pad -> banks (h+k)%32, conflict-free
    const int t0 = blockIdx.x * 64;
    const int h0 = blockIdx.y * 64;
    const int tid = threadIdx.x;

    for (int i = tid; i < 64 * NIN; i += 256)
        xs[i >> 6][i & 63] = x[(size_t)(t0 + (i >> 6)) * NIN + (i & 63)];
    for (int i = tid; i < 64 * NIN; i += 256)
        ws[i >> 6][i & 63] = w1[(size_t)(h0 + (i >> 6)) * NIN + (i & 63)];
    __syncthreads();

    const int h = tid & 63, tq = tid >> 6;
    float acc[16];
#pragma unroll
    for (int i = 0; i < 16; i++) acc[i] = 0.0f;

#pragma unroll 16
    for (int k = 0; k < NIN; k++) {
        const float wv = ws[h][k];
#pragma unroll
        for (int i = 0; i < 16; i++) acc[i] = fmaf(xs[tq * 16 + i][k], wv, acc[i]);
    }
    const float bb = b1[h0 + h];
#pragma unroll
    for (int i = 0; i < 16; i++) {
        float v = acc[i] + bb;
        v = (v >= 0.0f) ? v : 0.01f * v;
        out[(size_t)(t0 + tq * 16 + i) * HD + h0 + h] = v;
    }
}

// ---------------- input-projection GEMM: Z = X @ Wih^T + (b_ih + b_hh) -------
// classic 128x128x8 SGEMM, 256 threads, 8x8 accumulators per thread.
__global__ __launch_bounds__(256) void k_gemm(const float* __restrict__ A,   // (SEQ, HD)
                                              const float* __restrict__ W,   // (G4, HD)
                                              const float* __restrict__ bi,
                                              const float* __restrict__ bh) {
    __shared__ float As[8][128];
    __shared__ float Bs[8][128];
    const int tid = threadIdx.x;
    const int tx = tid & 15, ty = tid >> 4;
    const int m0 = blockIdx.y * 128, n0 = blockIdx.x * 128;
    const int lr = tid >> 1, lk = (tid & 1) * 4;

    const float* Ap = A + (size_t)(m0 + lr) * HD + lk;
    const float* Wp = W + (size_t)(n0 + lr) * HD + lk;

    float acc[8][8];
#pragma unroll
    for (int i = 0; i < 8; i++)
#pragma unroll
        for (int j = 0; j < 8; j++) acc[i][j] = 0.0f;

    for (int k0 = 0; k0 < HD; k0 += 8) {
        const float4 av = *(const float4*)(Ap + k0);
        const float4 bv = *(const float4*)(Wp + k0);
        __syncthreads();
        As[lk + 0][lr] = av.x; As[lk + 1][lr] = av.y; As[lk + 2][lr] = av.z; As[lk + 3][lr] = av.w;
        Bs[lk + 0][lr] = bv.x; Bs[lk + 1][lr] = bv.y; Bs[lk + 2][lr] = bv.z; Bs[lk + 3][lr] = bv.w;
        __syncthreads();
#pragma unroll
        for (int kk = 0; kk < 8; kk++) {
            float ar[8], br[8];
            *(float4*)(ar)     = *(const float4*)&As[kk][ty * 8];
            *(float4*)(ar + 4) = *(const float4*)&As[kk][ty * 8 + 4];
            *(float4*)(br)     = *(const float4*)&Bs[kk][tx * 8];
            *(float4*)(br + 4) = *(const float4*)&Bs[kk][tx * 8 + 4];
#pragma unroll
            for (int i = 0; i < 8; i++)
#pragma unroll
                for (int j = 0; j < 8; j++) acc[i][j] = fmaf(ar[i], br[j], acc[i][j]);
        }
    }
#pragma unroll
    for (int i = 0; i < 8; i++) {
        const size_t m = (size_t)(m0 + ty * 8 + i);
#pragma unroll
        for (int j = 0; j < 8; j++) {
            const int n = n0 + tx * 8 + j;
            g_Z[m * G4 + n] = acc[i][j] + bi[n] + bh[n];
        }
    }
}

// ---------------- prep: seed h buffer with h0[layer] -------------------------
__global__ void k_prep(const float* __restrict__ h0l) {
    const int i = threadIdx.x + blockIdx.x * blockDim.x;
    if (i < HD) g_h[HD + i] = h0l[i];   // t=0 reads buf[1]
}

// ---------------- recurrent persistent kernel --------------------------------
// 128 CTAs x 256 threads. CTA k: hidden units [k*8, k*8+8). warp w: unit u=k*8+w,
// owns gate rows {u, 1024+u, 2048+u, 3072+u}, weights live in registers (128/thread).
__global__ __launch_bounds__(256, 1) void k_rec(const float* __restrict__ Whh,  // (G4, HD)
                                                const float* __restrict__ c0l,  // (HD)
                                                float* __restrict__ Xout,       // (SEQ, HD)
                                                unsigned base) {
    __shared__ float sh[HD];
    const int tid = threadIdx.x;
    const int w = tid >> 5, lane = tid & 31;
    const int u = blockIdx.x * 8 + w;

    // load this warp's weight slice into registers (coalesced across lanes)
    float wr[4][32];
#pragma unroll
    for (int g = 0; g < 4; g++) {
        const float* rp = Whh + (size_t)(g * HD + u) * HD + lane;
#pragma unroll
        for (int j = 0; j < 32; j++) wr[g][j] = rp[j * 32];
    }
    float c = c0l[u];   // only lane 0's copy is used

#pragma unroll 1
    for (int t = 0; t < SEQ; t++) {
        // prefetch this step's input projection (independent of h)
        float z0 = 0.f, z1 = 0.f, z2 = 0.f, z3 = 0.f;
        if (lane == 0) {
            const float* zp = g_Z + (size_t)t * G4 + u;
            z0 = zp[0]; z1 = zp[HD]; z2 = zp[2 * HD]; z3 = zp[3 * HD];
        }
        // wait until all CTAs have posted step t-1
        if (tid == 0) {
            const unsigned target = base + (unsigned)t * NCTA;
            while (ld_acq(&g_counter) < target) {}
        }
        __syncthreads();
        // stage h_{t-1} into SMEM (L2-coherent loads)
        {
            const float4 v = __ldcg((const float4*)(g_h + ((t + 1) & 1) * HD) + tid);
            *(float4*)&sh[tid * 4] = v;
        }
        __syncthreads();

        float a0 = 0.f, a1 = 0.f, a2 = 0.f, a3 = 0.f;
#pragma unroll
        for (int j = 0; j < 32; j++) {
            const float hv = sh[lane + 32 * j];
            a0 = fmaf(wr[0][j], hv, a0);
            a1 = fmaf(wr[1][j], hv, a1);
            a2 = fmaf(wr[2][j], hv, a2);
            a3 = fmaf(wr[3][j], hv, a3);
        }
#pragma unroll
        for (int off = 16; off; off >>= 1) {
            a0 += __shfl_xor_sync(0xffffffffu, a0, off);
            a1 += __shfl_xor_sync(0xffffffffu, a1, off);
            a2 += __shfl_xor_sync(0xffffffffu, a2, off);
            a3 += __shfl_xor_sync(0xffffffffu, a3, off);
        }
        if (lane == 0) {
            const float ig = sigmf(a0 + z0);
            const float fg = sigmf(a1 + z1);
            const float gg = tanh_fast(a2 + z2);
            const float og = sigmf(a3 + z3);
            c = fg * c + ig * gg;
            const float h = og * tanh_fast(c);
            __stcg(g_h + (t & 1) * HD + u, h);          // broadcast buffer (L2)
            Xout[(size_t)t * HD + u] = h;               // sequence output
            __threadfence();                            // make h visible before post
        }
        __syncthreads();                                // all warps stored + fenced
        if (tid == 0) atomicAdd(&g_counter, 1u);        // post step t
    }
}

// ---------------- final: tanh(leaky_relu(X) @ w2^T + b2) ---------------------
// block: 64 timesteps x all 64 outputs, K tiled by 64.
__global__ __launch_bounds__(256) void k_final(const float* __restrict__ Xin,
                                               const float* __restrict__ w2,   // (NIN, HD)
                                               const float* __restrict__ b2,
                                               float* __restrict__ y) {
    __shared__ float xs[64][65];
    __shared__ float ws[64][65];
    const int t0 = blockIdx.x * 64;
    const int tid = threadIdx.x;
    const int o = tid & 63, tq = tid >> 6;

    float acc[16];
#pragma unroll
    for (int i = 0; i < 16; i++) acc[i] = 0.0f;

    for (int k0 = 0; k0 < HD; k0 += 64) {
        __syncthreads();
        for (int i = tid; i < 64 * 64; i += 256) {
            const int r = i >> 6, cc = i & 63;
            float v = Xin[(size_t)(t0 + r) * HD + k0 + cc];
            xs[r][cc] = (v >= 0.0f) ? v : 0.01f * v;       // leaky_relu
            ws[r][cc] = w2[(size_t)r * HD + k0 + cc];
        }
        __syncthreads();
#pragma unroll 16
        for (int k = 0; k < 64; k++) {
            const float wv = ws[o][k];
#pragma unroll
            for (int i = 0; i < 16; i++) acc[i] = fmaf(xs[tq * 16 + i][k], wv, acc[i]);
        }
    }
    const float bb = b2[o];
#pragma unroll
    for (int i = 0; i < 16; i++)
        y[(size_t)(t0 + tq * 16 + i) * NIN + o] = tanh_fast(acc[i] + bb);
}

// ---------------- host launcher ----------------------------------------------
extern "C" void kernel_launch(void* const* d_in, const int* in_sizes, int n_in,
                              void* d_out, int out_size) {
    const float* data_in = (const float*)d_in[0];
    const float* w1      = (const float*)d_in[1];
    const float* b1      = (const float*)d_in[2];
    const float* W_ih    = (const float*)d_in[3];
    const float* W_hh    = (const float*)d_in[4];
    const float* b_ih    = (const float*)d_in[5];
    const float* b_hh    = (const float*)d_in[6];
    const float* w2      = (const float*)d_in[7];
    const float* b2      = (const float*)d_in[8];
    const float* h0      = (const float*)d_in[9];
    const float* c0      = (const float*)d_in[10];
    float* out = (float*)d_out;

    static float* dA = nullptr;
    static float* dB = nullptr;
    if (!dA) {   // first call is the (uncaptured) correctness run; pure host query
        cudaGetSymbolAddress((void**)&dA, g_bufA);
        cudaGetSymbolAddress((void**)&dB, g_bufB);
    }
    float* bufs[2] = { dA, dB };

    k_init<<<1, 1>>>();
    k_first<<<dim3(SEQ / 64, HD / 64), 256>>>(data_in, w1, b1, dA);

    for (int l = 0; l < NLAYER; l++) {
        const float* Xin = bufs[l & 1];
        float* Xout = bufs[(l & 1) ^ 1];
        k_gemm<<<dim3(G4 / 128, SEQ / 128), 256>>>(Xin,
                                                   W_ih + (size_t)l * G4 * HD,
                                                   b_ih + (size_t)l * G4,
                                                   b_hh + (size_t)l * G4);
        k_prep<<<4, 256>>>(h0 + (size_t)l * HD);
        k_rec<<<NCTA, 256>>>(W_hh + (size_t)l * G4 * HD,
                             c0 + (size_t)l * HD,
                             Xout,
                             (unsigned)(l * SEQ * NCTA));
    }
    k_final<<<SEQ / 64, 256>>>(bufs[NLAYER & 1], w2, b2, out);
}

// round 2
// speedup vs baseline: 1.0712x; 1.0712x over previous
#include <cuda_runtime.h>

#define SEQ   8192
#define HD    1024
#define G4    4096
#define NIN   64
#define NLAYER 5
#define NCTA  128

// ---------------- scratch (device globals; no allocation allowed) ------------
__device__ float    g_bufA[(size_t)SEQ * HD];   // 32 MB activation ping
__device__ float    g_bufB[(size_t)SEQ * HD];   // 32 MB activation pong
__device__ float    g_Z[(size_t)SEQ * G4];      // 128 MB input-projection buffer
__device__ float    g_h[2 * HD];                // double-buffered hidden state
__device__ unsigned g_flags[NCTA];              // per-CTA monotonic step flags

// ---------------- math helpers ----------------------------------------------
__device__ __forceinline__ float sigmf(float x) { return 1.0f / (1.0f + __expf(-x)); }
__device__ __forceinline__ float tanh_fast(float x) { return 1.0f - 2.0f / (__expf(2.0f * x) + 1.0f); }

__device__ __forceinline__ unsigned ld_acq(const unsigned* p) {
    unsigned v;
    asm volatile("ld.acquire.gpu.global.b32 %0, [%1];" : "=r"(v) : "l"(p) : "memory");
    return v;
}
__device__ __forceinline__ void st_relx(unsigned* p, unsigned v) {
    asm volatile("st.relaxed.gpu.global.b32 [%0], %1;" :: "l"(p), "r"(v) : "memory");
}

// ---------------- init: reset flags ------------------------------------------
__global__ void k_init() { g_flags[threadIdx.x] = 0u; }

// ---------------- first layer: leaky_relu(x @ w1^T + b1) ---------------------
__global__ __launch_bounds__(256) void k_first(const float* __restrict__ x,
                                               const float* __restrict__ w1,
                                               const float* __restrict__ b1,
                                               float* __restrict__ out) {
    __shared__ float xs[64][NIN];
    __shared__ float ws[64][NIN + 1];
    const int t0 = blockIdx.x * 64;
    const int h0 = blockIdx.y * 64;
    const int tid = threadIdx.x;

    for (int i = tid; i < 64 * NIN; i += 256)
        xs[i >> 6][i & 63] = x[(size_t)(t0 + (i >> 6)) * NIN + (i & 63)];
    for (int i = tid; i < 64 * NIN; i += 256)
        ws[i >> 6][i & 63] = w1[(size_t)(h0 + (i >> 6)) * NIN + (i & 63)];
    __syncthreads();

    const int h = tid & 63, tq = tid >> 6;
    float acc[16];
#pragma unroll
    for (int i = 0; i < 16; i++) acc[i] = 0.0f;

#pragma unroll 16
    for (int k = 0; k < NIN; k++) {
        const float wv = ws[h][k];
#pragma unroll
        for (int i = 0; i < 16; i++) acc[i] = fmaf(xs[tq * 16 + i][k], wv, acc[i]);
    }
    const float bb = b1[h0 + h];
#pragma unroll
    for (int i = 0; i < 16; i++) {
        float v = acc[i] + bb;
        v = (v >= 0.0f) ? v : 0.01f * v;
        out[(size_t)(t0 + tq * 16 + i) * HD + h0 + h] = v;
    }
}

// ---------------- input-projection GEMM: Z = X @ Wih^T + (b_ih + b_hh) -------
// 128x128x8 SGEMM, 256 threads, 8x8 accumulators, register prefetch of next k-tile.
__global__ __launch_bounds__(256, 2) void k_gemm(const float* __restrict__ A,   // (SEQ, HD)
                                                 const float* __restrict__ W,   // (G4, HD)
                                                 const float* __restrict__ bi,
                                                 const float* __restrict__ bh) {
    __shared__ float As[8][128];
    __shared__ float Bs[8][128];
    const int tid = threadIdx.x;
    const int tx = tid & 15, ty = tid >> 4;
    const int m0 = blockIdx.y * 128, n0 = blockIdx.x * 128;
    const int lr = tid >> 1, lk = (tid & 1) * 4;

    const float* Ap = A + (size_t)(m0 + lr) * HD + lk;
    const float* Wp = W + (size_t)(n0 + lr) * HD + lk;

    float acc[8][8];
#pragma unroll
    for (int i = 0; i < 8; i++)
#pragma unroll
        for (int j = 0; j < 8; j++) acc[i][j] = 0.0f;

    float4 av = *(const float4*)(Ap);
    float4 bv = *(const float4*)(Wp);

    for (int k0 = 0; k0 < HD; k0 += 8) {
        __syncthreads();
        As[lk + 0][lr] = av.x; As[lk + 1][lr] = av.y; As[lk + 2][lr] = av.z; As[lk + 3][lr] = av.w;
        Bs[lk + 0][lr] = bv.x; Bs[lk + 1][lr] = bv.y; Bs[lk + 2][lr] = bv.z; Bs[lk + 3][lr] = bv.w;
        __syncthreads();
        if (k0 + 8 < HD) {                       // prefetch next tile while computing
            av = *(const float4*)(Ap + k0 + 8);
            bv = *(const float4*)(Wp + k0 + 8);
        }
#pragma unroll
        for (int kk = 0; kk < 8; kk++) {
            float ar[8], br[8];
            *(float4*)(ar)     = *(const float4*)&As[kk][ty * 8];
            *(float4*)(ar + 4) = *(const float4*)&As[kk][ty * 8 + 4];
            *(float4*)(br)     = *(const float4*)&Bs[kk][tx * 8];
            *(float4*)(br + 4) = *(const float4*)&Bs[kk][tx * 8 + 4];
#pragma unroll
            for (int i = 0; i < 8; i++)
#pragma unroll
                for (int j = 0; j < 8; j++) acc[i][j] = fmaf(ar[i], br[j], acc[i][j]);
        }
    }
    float bb[8];
#pragma unroll
    for (int j = 0; j < 8; j++) bb[j] = bi[n0 + tx * 8 + j] + bh[n0 + tx * 8 + j];
#pragma unroll
    for (int i = 0; i < 8; i++) {
        const size_t m = (size_t)(m0 + ty * 8 + i);
        float4 o0, o1;
        o0.x = acc[i][0] + bb[0]; o0.y = acc[i][1] + bb[1];
        o0.z = acc[i][2] + bb[2]; o0.w = acc[i][3] + bb[3];
        o1.x = acc[i][4] + bb[4]; o1.y = acc[i][5] + bb[5];
        o1.z = acc[i][6] + bb[6]; o1.w = acc[i][7] + bb[7];
        *(float4*)&g_Z[m * G4 + n0 + tx * 8]     = o0;
        *(float4*)&g_Z[m * G4 + n0 + tx * 8 + 4] = o1;
    }
}

// ---------------- prep: seed h buffer with h0[layer] -------------------------
__global__ void k_prep(const float* __restrict__ h0l) {
    const int i = threadIdx.x + blockIdx.x * blockDim.x;
    if (i < HD) g_h[HD + i] = h0l[i];   // t=0 reads buf[1]
}

// ---------------- recurrent persistent kernel --------------------------------
// 128 CTAs x 256 threads. CTA b owns units [8b, 8b+8); warp w handles unit u=8b+w,
// gate rows {u, 1024+u, 2048+u, 3072+u}. Weights in registers as f32x2 pairs:
// lane owns k in {64j+2*lane, 64j+2*lane+1}, j=0..15.
__global__ __launch_bounds__(256, 1) void k_rec(const float* __restrict__ Whh,  // (G4, HD)
                                                const float* __restrict__ c0l,  // (HD)
                                                float* __restrict__ Xout,       // (SEQ, HD)
                                                unsigned base) {
    __shared__ float sh[HD];
    const int tid = threadIdx.x;
    const int w = tid >> 5, lane = tid & 31;
    const int u = blockIdx.x * 8 + w;

    // shared-space byte address of this lane's pair base
    unsigned sb;
    asm("{ .reg .u64 t; cvta.to.shared.u64 t, %1; cvt.u32.u64 %0, t; }"
        : "=r"(sb) : "l"((void*)sh));
    sb += (unsigned)lane * 8u;

    // load packed weight pairs into registers (64 x b64 = 128 regs)
    unsigned long long wp[4][16];
#pragma unroll
    for (int g = 0; g < 4; g++) {
        const float* rp = Whh + (size_t)(g * HD + u) * HD + 2 * lane;
#pragma unroll
        for (int j = 0; j < 16; j++) {
            const float2 v = *(const float2*)(rp + 64 * j);
            asm("mov.b64 %0, {%1, %2};" : "=l"(wp[g][j]) : "f"(v.x), "f"(v.y));
        }
    }
    float c = c0l[u];   // only lane 0's copy is used

#pragma unroll 1
    for (int t = 0; t < SEQ; t++) {
        // prefetch this step's input projection (independent of h)
        float z0 = 0.f, z1 = 0.f, z2 = 0.f, z3 = 0.f;
        if (lane == 0) {
            const float* zp = g_Z + (size_t)t * G4 + u;
            z0 = zp[0]; z1 = zp[HD]; z2 = zp[2 * HD]; z3 = zp[3 * HD];
        }
        // each thread waits only for the CTA producing ITS float4 slice of h,
        // then loads it immediately (per-slice pipelining).
        {
            const unsigned target = base + (unsigned)t;
            const unsigned* fp = &g_flags[tid >> 1];
            while (ld_acq(fp) < target) {}
            const float4 v = __ldcg((const float4*)(g_h + ((t + 1) & 1) * HD) + tid);
            *(float4*)&sh[tid * 4] = v;
        }
        __syncthreads();

        // packed dot: 64 x fma.rn.f32x2 + 16 x LDS.64
        unsigned long long a0 = 0ull, a1 = 0ull, a2 = 0ull, a3 = 0ull;
#pragma unroll
        for (int j = 0; j < 16; j++) {
            unsigned long long hp;
            asm volatile("ld.shared.b64 %0, [%1];" : "=l"(hp) : "r"(sb + (unsigned)(j * 256)));
            asm("fma.rn.f32x2 %0, %1, %2, %0;" : "+l"(a0) : "l"(wp[0][j]), "l"(hp));
            asm("fma.rn.f32x2 %0, %1, %2, %0;" : "+l"(a1) : "l"(wp[1][j]), "l"(hp));
            asm("fma.rn.f32x2 %0, %1, %2, %0;" : "+l"(a2) : "l"(wp[2][j]), "l"(hp));
            asm("fma.rn.f32x2 %0, %1, %2, %0;" : "+l"(a3) : "l"(wp[3][j]), "l"(hp));
        }
        float s0, s1, s2, s3;
        {
            float x, y;
            asm("mov.b64 {%0,%1}, %2;" : "=f"(x), "=f"(y) : "l"(a0)); s0 = x + y;
            asm("mov.b64 {%0,%1}, %2;" : "=f"(x), "=f"(y) : "l"(a1)); s1 = x + y;
            asm("mov.b64 {%0,%1}, %2;" : "=f"(x), "=f"(y) : "l"(a2)); s2 = x + y;
            asm("mov.b64 {%0,%1}, %2;" : "=f"(x), "=f"(y) : "l"(a3)); s3 = x + y;
        }
#pragma unroll
        for (int off = 16; off; off >>= 1) {
            s0 += __shfl_xor_sync(0xffffffffu, s0, off);
            s1 += __shfl_xor_sync(0xffffffffu, s1, off);
            s2 += __shfl_xor_sync(0xffffffffu, s2, off);
            s3 += __shfl_xor_sync(0xffffffffu, s3, off);
        }
        float h = 0.f;
        if (lane == 0) {
            const float ig = sigmf(s0 + z0);
            const float fg = sigmf(s1 + z1);
            const float gg = tanh_fast(s2 + z2);
            const float og = sigmf(s3 + z3);
            c = fg * c + ig * gg;
            h = og * tanh_fast(c);
            __stcg(g_h + (t & 1) * HD + u, h);          // broadcast buffer (L2)
        }
        __syncthreads();                                // all 8 warps' h stores done
        if (tid == 0) {
            __threadfence();                            // publish h stores (cumulative)
            st_relx(&g_flags[blockIdx.x], base + (unsigned)t + 1u);
        }
        if (lane == 0)
            Xout[(size_t)t * HD + u] = h;               // off the critical path
    }
}

// ---------------- final: tanh(leaky_relu(X) @ w2^T + b2) ---------------------
__global__ __launch_bounds__(256) void k_final(const float* __restrict__ Xin,
                                               const float* __restrict__ w2,   // (NIN, HD)
                                               const float* __restrict__ b2,
                                               float* __restrict__ y) {
    __shared__ float xs[64][65];
    __shared__ float ws[64][65];
    const int t0 = blockIdx.x * 64;
    const int tid = threadIdx.x;
    const int o = tid & 63, tq = tid >> 6;

    float acc[16];
#pragma unroll
    for (int i = 0; i < 16; i++) acc[i] = 0.0f;

    for (int k0 = 0; k0 < HD; k0 += 64) {
        __syncthreads();
        for (int i = tid; i < 64 * 64; i += 256) {
            const int r = i >> 6, cc = i & 63;
            float v = Xin[(size_t)(t0 + r) * HD + k0 + cc];
            xs[r][cc] = (v >= 0.0f) ? v : 0.01f * v;       // leaky_relu
            ws[r][cc] = w2[(size_t)r * HD + k0 + cc];
        }
        __syncthreads();
#pragma unroll 16
        for (int k = 0; k < 64; k++) {
            const float wv = ws[o][k];
#pragma unroll
            for (int i = 0; i < 16; i++) acc[i] = fmaf(xs[tq * 16 + i][k], wv, acc[i]);
        }
    }
    const float bb = b2[o];
#pragma unroll
    for (int i = 0; i < 16; i++)
        y[(size_t)(t0 + tq * 16 + i) * NIN + o] = tanh_fast(acc[i] + bb);
}

// ---------------- host launcher ----------------------------------------------
extern "C" void kernel_launch(void* const* d_in, const int* in_sizes, int n_in,
                              void* d_out, int out_size) {
    const float* data_in = (const float*)d_in[0];
    const float* w1      = (const float*)d_in[1];
    const float* b1      = (const float*)d_in[2];
    const float* W_ih    = (const float*)d_in[3];
    const float* W_hh    = (const float*)d_in[4];
    const float* b_ih    = (const float*)d_in[5];
    const float* b_hh    = (const float*)d_in[6];
    const float* w2      = (const float*)d_in[7];
    const float* b2      = (const float*)d_in[8];
    const float* h0      = (const float*)d_in[9];
    const float* c0      = (const float*)d_in[10];
    float* out = (float*)d_out;

    static float* dA = nullptr;
    static float* dB = nullptr;
    if (!dA) {   // host-side symbol query, not an allocation
        cudaGetSymbolAddress((void**)&dA, g_bufA);
        cudaGetSymbolAddress((void**)&dB, g_bufB);
    }
    float* bufs[2] = { dA, dB };

    k_init<<<1, NCTA>>>();
    k_first<<<dim3(SEQ / 64, HD / 64), 256>>>(data_in, w1, b1, dA);

    for (int l = 0; l < NLAYER; l++) {
        const float* Xin = bufs[l & 1];
        float* Xout = bufs[(l & 1) ^ 1];
        k_gemm<<<dim3(G4 / 128, SEQ / 128), 256>>>(Xin,
                                                   W_ih + (size_t)l * G4 * HD,
                                                   b_ih + (size_t)l * G4,
                                                   b_hh + (size_t)l * G4);
        k_prep<<<4, 256>>>(h0 + (size_t)l * HD);
        k_rec<<<NCTA, 256>>>(W_hh + (size_t)l * G4 * HD,
                             c0 + (size_t)l * HD,
                             Xout,
                             (unsigned)(l * SEQ));
    }
    k_final<<<SEQ / 64, 256>>>(bufs[NLAYER & 1], w2, b2, out);
}